// round 1
// baseline (speedup 1.0000x reference)
#include <cuda_runtime.h>
#include <math.h>

#define BB    8
#define CIN   64
#define CR    32
#define HEADS 4
#define RDIM  128   // HEADS*CR
#define HH    128
#define WW    128
#define NN    16384 // HH*WW
#define COUT  64
#define CNT   (BB * NN)   // elements per channel for BN: 131072

// ---------------- device scratch (static allocation: allowed) ----------------
__device__ float g_Wc[RDIM * CIN];                       // combined lin@reduce  [r][c]
__device__ float g_hfeat[(size_t)BB * NN * RDIM];        // [b*N + n][r]         64 MB
__device__ float g_att[(size_t)BB * NN * 8];             // per node: a_s[4], a_d[4]
__device__ float g_pre[(size_t)BB * COUT * NN];          // pre-BN output        33.5 MB
__device__ float g_sum[COUT];
__device__ float g_sumsq[COUT];
__device__ float g_scale[COUT];
__device__ float g_shift[COUT];

// ---------------- kernel 0: Wc = w_lin @ w_reduce, zero BN stats -------------
__global__ void k_prep(const float* __restrict__ w_lin,     // [128][32]
                       const float* __restrict__ w_reduce)  // [32][64]
{
    int idx = blockIdx.x * blockDim.x + threadIdx.x;
    if (idx < RDIM * CIN) {
        int r = idx >> 6;       // /64
        int c = idx & 63;
        float acc = 0.f;
        #pragma unroll
        for (int k = 0; k < CR; k++)
            acc += w_lin[r * CR + k] * w_reduce[k * CIN + c];
        g_Wc[idx] = acc;
    }
    if (idx < COUT) { g_sum[idx] = 0.f; g_sumsq[idx] = 0.f; }
}

// ---------------- kernel A: hfeat = Wc @ x, plus a_s/a_d ---------------------
// block: 256 threads, 32 nodes. thread (tr=t%32, tn=t/32) computes r=4*tr..+3,
// n = 4*tn..+3 micro-tile. 64-deep K loop over input channels.
__global__ __launch_bounds__(256) void k_hfeat(
    const float* __restrict__ x,        // [B][CIN][N]
    const float* __restrict__ att_src,  // [H][CR]
    const float* __restrict__ att_dst)  // [H][CR]
{
    __shared__ float xs[CIN * 32];      // [c][n]   stride 32
    __shared__ float Wcs[CIN * 132];    // [c][r]   stride 132 (pad: banks + 16B align)

    const int t  = threadIdx.x;
    const int b  = blockIdx.x >> 9;            // /512
    const int nodeBase = (blockIdx.x & 511) << 5;
    const int tr = t & 31;
    const int tn = t >> 5;

    // load x tile [64 c][32 n]
    #pragma unroll
    for (int it = 0; it < 8; it++) {
        int c = (t >> 5) + it * 8;
        int n = t & 31;
        xs[c * 32 + n] = x[((size_t)(b * CIN + c)) * NN + nodeBase + n];
    }
    // load Wc transposed into shared [c][r]
    #pragma unroll
    for (int k = 0; k < 32; k++) {
        int idx = t + k * 256;
        int r = idx >> 6;
        int c = idx & 63;
        Wcs[c * 132 + r] = g_Wc[idx];
    }
    __syncthreads();

    float acc[4][4];   // [k (r offset)][nn]
    #pragma unroll
    for (int k = 0; k < 4; k++)
        #pragma unroll
        for (int nn = 0; nn < 4; nn++) acc[k][nn] = 0.f;

    #pragma unroll
    for (int c = 0; c < CIN; c++) {
        float4 wv = *(const float4*)&Wcs[c * 132 + (tr << 2)];
        float4 xv = *(const float4*)&xs[(c << 5) + (tn << 2)];
        acc[0][0] += wv.x * xv.x; acc[0][1] += wv.x * xv.y; acc[0][2] += wv.x * xv.z; acc[0][3] += wv.x * xv.w;
        acc[1][0] += wv.y * xv.x; acc[1][1] += wv.y * xv.y; acc[1][2] += wv.y * xv.z; acc[1][3] += wv.y * xv.w;
        acc[2][0] += wv.z * xv.x; acc[2][1] += wv.z * xv.y; acc[2][2] += wv.z * xv.z; acc[2][3] += wv.z * xv.w;
        acc[3][0] += wv.w * xv.x; acc[3][1] += wv.w * xv.y; acc[3][2] += wv.w * xv.z; acc[3][3] += wv.w * xv.w;
    }

    // store hfeat (coalesced float4 across warp: lanes tr cover r=0..127)
    const int node0 = nodeBase + (tn << 2);
    #pragma unroll
    for (int nn = 0; nn < 4; nn++) {
        float4 hv = make_float4(acc[0][nn], acc[1][nn], acc[2][nn], acc[3][nn]);
        *(float4*)&g_hfeat[((size_t)(b * NN + node0 + nn)) * RDIM + (tr << 2)] = hv;
    }

    // attention scalars: this lane owns r = 4*tr..4*tr+3, all within head h = tr/8.
    const int h   = tr >> 3;
    const int kk0 = (tr & 7) << 2;
    float asv[4], adv[4];
    #pragma unroll
    for (int k = 0; k < 4; k++) {
        asv[k] = att_src[h * CR + kk0 + k];
        adv[k] = att_dst[h * CR + kk0 + k];
    }
    #pragma unroll
    for (int nn = 0; nn < 4; nn++) {
        float ps = acc[0][nn] * asv[0] + acc[1][nn] * asv[1] + acc[2][nn] * asv[2] + acc[3][nn] * asv[3];
        float pd = acc[0][nn] * adv[0] + acc[1][nn] * adv[1] + acc[2][nn] * adv[2] + acc[3][nn] * adv[3];
        #pragma unroll
        for (int off = 1; off < 8; off <<= 1) {
            ps += __shfl_xor_sync(0xffffffffu, ps, off);
            pd += __shfl_xor_sync(0xffffffffu, pd, off);
        }
        if ((tr & 7) == 0) {
            size_t vg = (size_t)(b * NN + node0 + nn);
            g_att[vg * 8 + h]     = ps;
            g_att[vg * 8 + 4 + h] = pd;
        }
    }
}

// ---------------- kernel B: GAT aggregation + restore + residual + BN stats --
// 1024 threads: phase1 = warp-per-node (32 nodes/block), phase2 = warp-per-out-channel.
__global__ __launch_bounds__(1024, 1) void k_agg(
    const float* __restrict__ x,         // residual [B][COUT][N] (CIN==COUT)
    const float* __restrict__ w_restore, // [64][32]
    const float* __restrict__ b_gat)     // [32]
{
    __shared__ float Wr_s[COUT * CR];    // 8 KB
    __shared__ float nf[32 * 33];        // node features, padded

    const int t    = threadIdx.x;
    const int b    = blockIdx.x >> 9;
    const int nodeBase = (blockIdx.x & 511) << 5;
    const int warp = t >> 5;
    const int lane = t & 31;

    // load restore weights
    Wr_s[t]        = w_restore[t];
    Wr_s[t + 1024] = w_restore[t + 1024];

    // ---- phase 1: per-node softmax-weighted neighbor aggregation ----
    {
        const int n  = nodeBase + warp;
        const int i  = n >> 7;
        const int j  = n & 127;
        const int vg = b * NN + n;

        int  u[5];
        bool ok[5];
        u[0] = vg;              ok[0] = true;
        u[1] = vg - WW;         ok[1] = (i > 0);
        u[2] = vg + WW;         ok[2] = (i < HH - 1);
        u[3] = vg - 1;          ok[3] = (j > 0);
        u[4] = vg + 1;          ok[4] = (j < WW - 1);
        #pragma unroll
        for (int s = 0; s < 5; s++) if (!ok[s]) u[s] = vg;   // safe address

        float ad[4];
        #pragma unroll
        for (int hh = 0; hh < 4; hh++) ad[hh] = g_att[(size_t)vg * 8 + 4 + hh];

        float e[5][4], mx[4];
        #pragma unroll
        for (int hh = 0; hh < 4; hh++) mx[hh] = -1e30f;
        #pragma unroll
        for (int s = 0; s < 5; s++) {
            #pragma unroll
            for (int hh = 0; hh < 4; hh++) {
                float v = g_att[(size_t)u[s] * 8 + hh] + ad[hh];
                v = v > 0.f ? v : 0.2f * v;          // leaky_relu(0.2)
                if (!ok[s]) v = -1e30f;
                e[s][hh] = v;
                mx[hh] = fmaxf(mx[hh], v);
            }
        }
        float den[4] = {0.f, 0.f, 0.f, 0.f};
        #pragma unroll
        for (int s = 0; s < 5; s++) {
            #pragma unroll
            for (int hh = 0; hh < 4; hh++) {
                float v = __expf(e[s][hh] - mx[hh]);
                e[s][hh] = v;
                den[hh] += v;
            }
        }
        #pragma unroll
        for (int hh = 0; hh < 4; hh++) den[hh] = 1.f / den[hh];

        float acc[4] = {0.f, 0.f, 0.f, 0.f};
        #pragma unroll
        for (int s = 0; s < 5; s++) {
            const float* hp = &g_hfeat[(size_t)u[s] * RDIM + lane];
            #pragma unroll
            for (int hh = 0; hh < 4; hh++)
                acc[hh] += e[s][hh] * __ldg(hp + hh * 32);
        }
        float nfv = 0.25f * (acc[0] * den[0] + acc[1] * den[1] +
                             acc[2] * den[2] + acc[3] * den[3]) + b_gat[lane];
        nf[warp * 33 + lane] = nfv;
    }
    __syncthreads();

    // ---- phase 2: restore matvec + residual + per-channel stats ----
    {
        const int o  = warp;        // out channel (and o+32)
        const int nd = lane;        // node within block
        float v0 = 0.f, v1 = 0.f;
        #pragma unroll
        for (int c = 0; c < CR; c++) {
            float nfc = nf[nd * 33 + c];
            v0 += Wr_s[o * CR + c]        * nfc;
            v1 += Wr_s[(o + 32) * CR + c] * nfc;
        }
        size_t base0 = ((size_t)(b * COUT + o))      * NN + nodeBase + nd;
        size_t base1 = ((size_t)(b * COUT + o + 32)) * NN + nodeBase + nd;
        v0 += x[base0];
        v1 += x[base1];
        g_pre[base0] = v0;
        g_pre[base1] = v1;

        float s0 = v0, q0 = v0 * v0, s1 = v1, q1 = v1 * v1;
        #pragma unroll
        for (int off = 16; off > 0; off >>= 1) {
            s0 += __shfl_xor_sync(0xffffffffu, s0, off);
            q0 += __shfl_xor_sync(0xffffffffu, q0, off);
            s1 += __shfl_xor_sync(0xffffffffu, s1, off);
            q1 += __shfl_xor_sync(0xffffffffu, q1, off);
        }
        if (lane == 0) {
            atomicAdd(&g_sum[o],        s0);
            atomicAdd(&g_sumsq[o],      q0);
            atomicAdd(&g_sum[o + 32],   s1);
            atomicAdd(&g_sumsq[o + 32], q1);
        }
    }
}

// ---------------- kernel C: finalize BN scale/shift --------------------------
__global__ void k_bnstats(const float* __restrict__ gamma,
                          const float* __restrict__ beta)
{
    int c = threadIdx.x;
    float inv_cnt = 1.f / (float)CNT;
    float mean = g_sum[c] * inv_cnt;
    float var  = g_sumsq[c] * inv_cnt - mean * mean;
    float sc   = gamma[c] / sqrtf(var + 1e-5f);
    g_scale[c] = sc;
    g_shift[c] = beta[c] - mean * sc;
}

// ---------------- kernel D: normalize + relu ---------------------------------
__global__ __launch_bounds__(256) void k_bnrelu(float* __restrict__ out)
{
    int idx = blockIdx.x * blockDim.x + threadIdx.x;   // float4 index
    int c = (idx >> 12) & 63;                          // (idx*4 / 16384) % 64
    float sc = g_scale[c], sh = g_shift[c];
    float4 v = *(const float4*)&g_pre[(size_t)idx * 4];
    v.x = fmaxf(0.f, v.x * sc + sh);
    v.y = fmaxf(0.f, v.y * sc + sh);
    v.z = fmaxf(0.f, v.z * sc + sh);
    v.w = fmaxf(0.f, v.w * sc + sh);
    *(float4*)&out[(size_t)idx * 4] = v;
}

// ---------------- launch ------------------------------------------------------
extern "C" void kernel_launch(void* const* d_in, const int* in_sizes, int n_in,
                              void* d_out, int out_size)
{
    const float* x         = (const float*)d_in[0];
    const float* w_reduce  = (const float*)d_in[1];
    const float* w_lin     = (const float*)d_in[2];
    const float* att_src   = (const float*)d_in[3];
    const float* att_dst   = (const float*)d_in[4];
    const float* b_gat     = (const float*)d_in[5];
    const float* w_restore = (const float*)d_in[6];
    const float* bn_gamma  = (const float*)d_in[7];
    const float* bn_beta   = (const float*)d_in[8];
    // d_in[9]=src, d_in[10]=dst: structured grid — recomputed analytically.

    k_prep<<<32, 256>>>(w_lin, w_reduce);
    k_hfeat<<<BB * NN / 32, 256>>>(x, att_src, att_dst);
    k_agg<<<BB * NN / 32, 1024>>>(x, w_restore, b_gat);
    k_bnstats<<<1, 64>>>(bn_gamma, bn_beta);
    k_bnrelu<<<(BB * COUT * NN / 4) / 256, 256>>>((float*)d_out);
}

// round 3
// speedup vs baseline: 1.7535x; 1.7535x over previous
#include <cuda_runtime.h>
#include <math.h>

#define BB    8
#define CIN   64
#define CR    32
#define RDIM  128
#define HH    128
#define WW    128
#define NN    16384
#define COUT  64
#define CNT   (BB * NN)

// ---------------- device scratch ----------------
__device__ float g_q[8 * CR];                        // rows 0-3: q_src[h], 4-7: q_dst[h]
__device__ float g_hfeat[(size_t)BB * NN * RDIM];    // [node][r]  64 MB
__device__ float g_att[(size_t)BB * NN * 8];         // [node][a_s0..3, a_d0..3]
__device__ float g_nf[(size_t)BB * NN * CR];         // aggregated node features 16 MB
__device__ float g_pre[(size_t)BB * COUT * NN];      // pre-BN 33.5 MB
__device__ float g_sum[COUT];
__device__ float g_sumsq[COUT];
__device__ float g_scale[COUT];
__device__ float g_shift[COUT];

// ---------------- kernel 0: q-vectors + zero stats ----------------
// q_s[h][k] = sum_c att_src[h][c] * w_lin[h*32+c][k]   (attention is linear in xr)
__global__ void k_prep(const float* __restrict__ w_lin,
                       const float* __restrict__ att_src,
                       const float* __restrict__ att_dst)
{
    int idx = threadIdx.x;
    if (idx < 256) {
        int rq = idx >> 5, k = idx & 31;
        int h = rq & 3;
        const float* av = (rq < 4) ? att_src : att_dst;
        float acc = 0.f;
        #pragma unroll
        for (int c = 0; c < CR; c++)
            acc += av[h * CR + c] * w_lin[(h * CR + c) * CR + k];
        g_q[rq * CR + k] = acc;
    }
    if (idx < COUT) { g_sum[idx] = 0.f; g_sumsq[idx] = 0.f; }
}

// ---------------- kernel A: two-stage projection + attention rows ----------
// 128 nodes / block, 512 threads.
// stage1: xr[32][128] = w_reduce @ x-tile
// stage2: hfeat[128][128] = w_lin @ xr    (+ 8 attention rows from q-vectors)
__global__ __launch_bounds__(512) void k_hfeat(
    const float* __restrict__ x,
    const float* __restrict__ w_reduce,
    const float* __restrict__ w_lin)
{
    __shared__ float S[8192];          // phase A: xs[64][128]; phase B: xr[32][128] | wl[32][128]
    __shared__ float wr_s[64 * 36];    // [c][cr], padded
    __shared__ float qs[256];          // [k][rq]

    const int t = threadIdx.x;
    const int b = blockIdx.x >> 7;                 // 128 blocks per batch
    const int nodeBase = (blockIdx.x & 127) << 7;
    const size_t vgbase = (size_t)b * NN + nodeBase;

    // load x tile [64 c][128 n] (coalesced)
    #pragma unroll
    for (int i = 0; i < 16; i++) {
        int idx = t + i * 512;
        int c = idx >> 7, n = idx & 127;
        S[idx] = x[((size_t)(b * CIN + c)) * NN + nodeBase + n];
    }
    // w_reduce transposed -> wr_s[c][cr]
    #pragma unroll
    for (int i = 0; i < 4; i++) {
        int idx = t + i * 512;
        int cr = idx >> 6, c = idx & 63;
        wr_s[c * 36 + cr] = w_reduce[idx];
    }
    if (t < 256) qs[(t & 31) * 8 + (t >> 5)] = g_q[t];
    __syncthreads();

    // ---- stage 1: xr = w_reduce @ xs ----
    const int crq  = t & 7;          // cr block: 4*crq..+3
    const int n1   = (t >> 3) * 2;   // node pair
    float a1[4][2];
    #pragma unroll
    for (int i = 0; i < 4; i++) { a1[i][0] = 0.f; a1[i][1] = 0.f; }
    #pragma unroll
    for (int c = 0; c < CIN; c++) {
        float4 wv = *(const float4*)&wr_s[c * 36 + crq * 4];
        float x0 = S[c * 128 + n1];
        float x1 = S[c * 128 + n1 + 1];
        a1[0][0] += wv.x * x0; a1[0][1] += wv.x * x1;
        a1[1][0] += wv.y * x0; a1[1][1] += wv.y * x1;
        a1[2][0] += wv.z * x0; a1[2][1] += wv.z * x1;
        a1[3][0] += wv.w * x0; a1[3][1] += wv.w * x1;
    }
    __syncthreads();

    // write xr -> S[0..4095], load w_lin transposed -> S[4096..8191] ([k][r])
    #pragma unroll
    for (int i = 0; i < 4; i++) {
        S[(crq * 4 + i) * 128 + n1]     = a1[i][0];
        S[(crq * 4 + i) * 128 + n1 + 1] = a1[i][1];
    }
    #pragma unroll
    for (int i = 0; i < 8; i++) {
        int idx = t + i * 512;
        int k = idx >> 7, r = idx & 127;
        S[4096 + idx] = w_lin[r * CR + k];
    }
    __syncthreads();

    // ---- stage 2: hfeat = w_lin @ xr ----
    const int tr = t & 31;      // r block: 4*tr..+3
    const int tn = t >> 5;      // node block: 8*tn..+7
    const int n0 = tn << 3;
    float acc[4][8];
    #pragma unroll
    for (int i = 0; i < 4; i++)
        #pragma unroll
        for (int j = 0; j < 8; j++) acc[i][j] = 0.f;

    #pragma unroll
    for (int k = 0; k < CR; k++) {
        float4 wv = *(const float4*)&S[4096 + k * 128 + tr * 4];
        float4 xa = *(const float4*)&S[k * 128 + n0];
        float4 xb = *(const float4*)&S[k * 128 + n0 + 4];
        acc[0][0] += wv.x * xa.x; acc[0][1] += wv.x * xa.y; acc[0][2] += wv.x * xa.z; acc[0][3] += wv.x * xa.w;
        acc[0][4] += wv.x * xb.x; acc[0][5] += wv.x * xb.y; acc[0][6] += wv.x * xb.z; acc[0][7] += wv.x * xb.w;
        acc[1][0] += wv.y * xa.x; acc[1][1] += wv.y * xa.y; acc[1][2] += wv.y * xa.z; acc[1][3] += wv.y * xa.w;
        acc[1][4] += wv.y * xb.x; acc[1][5] += wv.y * xb.y; acc[1][6] += wv.y * xb.z; acc[1][7] += wv.y * xb.w;
        acc[2][0] += wv.z * xa.x; acc[2][1] += wv.z * xa.y; acc[2][2] += wv.z * xa.z; acc[2][3] += wv.z * xa.w;
        acc[2][4] += wv.z * xb.x; acc[2][5] += wv.z * xb.y; acc[2][6] += wv.z * xb.z; acc[2][7] += wv.z * xb.w;
        acc[3][0] += wv.w * xa.x; acc[3][1] += wv.w * xa.y; acc[3][2] += wv.w * xa.z; acc[3][3] += wv.w * xa.w;
        acc[3][4] += wv.w * xb.x; acc[3][5] += wv.w * xb.y; acc[3][6] += wv.w * xb.z; acc[3][7] += wv.w * xb.w;
    }

    // ---- attention rows: a = q @ xr (8 rows) ----
    {
        const int rq = t & 7;
        const int np = t >> 3;          // node pair 0..63
        float p0 = 0.f, p1 = 0.f;
        #pragma unroll
        for (int k = 0; k < CR; k++) {
            float qv = qs[k * 8 + rq];
            p0 += qv * S[k * 128 + np * 2];
            p1 += qv * S[k * 128 + np * 2 + 1];
        }
        g_att[(vgbase + np * 2) * 8 + rq]     = p0;
        g_att[(vgbase + np * 2 + 1) * 8 + rq] = p1;
    }

    // ---- store hfeat (coalesced float4 rows) ----
    #pragma unroll
    for (int nn = 0; nn < 8; nn++) {
        float4 hv = make_float4(acc[0][nn], acc[1][nn], acc[2][nn], acc[3][nn]);
        *(float4*)&g_hfeat[(vgbase + n0 + nn) * RDIM + tr * 4] = hv;
    }
}

// ---------------- kernel B1: stencil softmax aggregation -> nf -------------
// warp per node, lane owns channels 4*lane..+3 (head = lane>>3).
__global__ __launch_bounds__(256) void k_agg(const float* __restrict__ b_gat)
{
    const int t = threadIdx.x, lane = t & 31, warp = t >> 5;
    const int b = blockIdx.x >> 11;                  // 2048 blocks per batch
    const int n = ((blockIdx.x & 2047) << 3) + warp;
    const int i = n >> 7, j = n & 127;
    const size_t vg = (size_t)b * NN + n;

    size_t u[5]; bool ok[5];
    u[0] = vg;       ok[0] = true;
    u[1] = vg - WW;  ok[1] = (i > 0);
    u[2] = vg + WW;  ok[2] = (i < HH - 1);
    u[3] = vg - 1;   ok[3] = (j > 0);
    u[4] = vg + 1;   ok[4] = (j < WW - 1);
    #pragma unroll
    for (int s = 0; s < 5; s++) if (!ok[s]) u[s] = vg;

    const int h = lane >> 3;
    const float ad = g_att[vg * 8 + 4 + h];

    float e[5], mx = -1e30f;
    #pragma unroll
    for (int s = 0; s < 5; s++) {
        float v = g_att[u[s] * 8 + h] + ad;
        v = v > 0.f ? v : 0.2f * v;        // leaky_relu(0.2)
        if (!ok[s]) v = -1e30f;
        e[s] = v;
        mx = fmaxf(mx, v);
    }
    float den = 0.f;
    #pragma unroll
    for (int s = 0; s < 5; s++) { e[s] = __expf(e[s] - mx); den += e[s]; }

    float4 acc = make_float4(0.f, 0.f, 0.f, 0.f);
    #pragma unroll
    for (int s = 0; s < 5; s++) {
        float4 hv = *(const float4*)&g_hfeat[u[s] * RDIM + lane * 4];
        acc.x += e[s] * hv.x; acc.y += e[s] * hv.y;
        acc.z += e[s] * hv.z; acc.w += e[s] * hv.w;
    }
    const float sc = 0.25f / den;          // normalize + head-mean factor
    acc.x *= sc; acc.y *= sc; acc.z *= sc; acc.w *= sc;

    // head-mean: sum lanes {l, l^8, l^16, l^24} (same channels, different heads)
    #pragma unroll
    for (int m = 8; m <= 16; m <<= 1) {
        acc.x += __shfl_xor_sync(0xffffffffu, acc.x, m);
        acc.y += __shfl_xor_sync(0xffffffffu, acc.y, m);
        acc.z += __shfl_xor_sync(0xffffffffu, acc.z, m);
        acc.w += __shfl_xor_sync(0xffffffffu, acc.w, m);
    }
    if (lane < 8) {
        int c0 = lane * 4;
        float4 o = make_float4(acc.x + b_gat[c0],     acc.y + b_gat[c0 + 1],
                               acc.z + b_gat[c0 + 2], acc.w + b_gat[c0 + 3]);
        *(float4*)&g_nf[vg * CR + c0] = o;
    }
}

// ---------------- kernel B2: restore GEMM + residual + BN stats ------------
// 64 nodes / block, 256 threads, microtile 4r x 4n, K=32.
__global__ __launch_bounds__(256) void k_restore(
    const float* __restrict__ x,
    const float* __restrict__ w_restore)
{
    __shared__ float  nfs[32 * 68];    // [k][n]
    __shared__ float  wrs[32 * 68];    // [k][o]
    __shared__ float2 red[64 * 17];    // per-channel (sum, sumsq) partials

    const int t = threadIdx.x;
    const int b = blockIdx.x >> 8;                 // 256 blocks per batch
    const int nodeBase = (blockIdx.x & 255) << 6;
    const size_t vgbase = (size_t)b * NN + nodeBase;

    #pragma unroll
    for (int i = 0; i < 8; i++) {
        int idx = t + i * 256;
        int n = idx >> 5, k = idx & 31;
        nfs[k * 68 + n] = g_nf[(vgbase + n) * CR + k];
    }
    #pragma unroll
    for (int i = 0; i < 8; i++) {
        int idx = t + i * 256;
        int o = idx >> 5, k = idx & 31;
        wrs[k * 68 + o] = w_restore[idx];
    }
    __syncthreads();

    const int tr = t & 15, tn = t >> 4;
    const int r0 = tr * 4, n0 = tn * 4;
    float acc[4][4];
    #pragma unroll
    for (int i = 0; i < 4; i++)
        #pragma unroll
        for (int j = 0; j < 4; j++) acc[i][j] = 0.f;

    #pragma unroll
    for (int k = 0; k < CR; k++) {
        float4 wv = *(const float4*)&wrs[k * 68 + r0];
        float4 xv = *(const float4*)&nfs[k * 68 + n0];
        acc[0][0] += wv.x * xv.x; acc[0][1] += wv.x * xv.y; acc[0][2] += wv.x * xv.z; acc[0][3] += wv.x * xv.w;
        acc[1][0] += wv.y * xv.x; acc[1][1] += wv.y * xv.y; acc[1][2] += wv.y * xv.z; acc[1][3] += wv.y * xv.w;
        acc[2][0] += wv.z * xv.x; acc[2][1] += wv.z * xv.y; acc[2][2] += wv.z * xv.z; acc[2][3] += wv.z * xv.w;
        acc[3][0] += wv.w * xv.x; acc[3][1] += wv.w * xv.y; acc[3][2] += wv.w * xv.z; acc[3][3] += wv.w * xv.w;
    }

    #pragma unroll
    for (int i = 0; i < 4; i++) {
        size_t base = ((size_t)(b * COUT + r0 + i)) * NN + nodeBase + n0;
        float4 rv = *(const float4*)&x[base];
        float4 v  = make_float4(acc[i][0] + rv.x, acc[i][1] + rv.y,
                                acc[i][2] + rv.z, acc[i][3] + rv.w);
        *(float4*)&g_pre[base] = v;
        float s = v.x + v.y + v.z + v.w;
        float q = v.x * v.x + v.y * v.y + v.z * v.z + v.w * v.w;
        red[(r0 + i) * 17 + tn] = make_float2(s, q);
    }
    __syncthreads();

    if (t < COUT) {
        float s = 0.f, q = 0.f;
        #pragma unroll
        for (int jj = 0; jj < 16; jj++) {
            float2 v = red[t * 17 + jj];
            s += v.x; q += v.y;
        }
        atomicAdd(&g_sum[t],   s);
        atomicAdd(&g_sumsq[t], q);
    }
}

// ---------------- kernel C: finalize BN scale/shift ------------------------
__global__ void k_bnstats(const float* __restrict__ gamma,
                          const float* __restrict__ beta)
{
    int c = threadIdx.x;
    float inv_cnt = 1.f / (float)CNT;
    float mean = g_sum[c] * inv_cnt;
    float var  = g_sumsq[c] * inv_cnt - mean * mean;
    float sc   = gamma[c] / sqrtf(var + 1e-5f);
    g_scale[c] = sc;
    g_shift[c] = beta[c] - mean * sc;
}

// ---------------- kernel D: normalize + relu -------------------------------
__global__ __launch_bounds__(256) void k_bnrelu(float* __restrict__ out)
{
    int idx = blockIdx.x * blockDim.x + threadIdx.x;   // float4 index
    int c = (idx >> 12) & 63;
    float sc = g_scale[c], sh = g_shift[c];
    float4 v = *(const float4*)&g_pre[(size_t)idx * 4];
    v.x = fmaxf(0.f, v.x * sc + sh);
    v.y = fmaxf(0.f, v.y * sc + sh);
    v.z = fmaxf(0.f, v.z * sc + sh);
    v.w = fmaxf(0.f, v.w * sc + sh);
    *(float4*)&out[(size_t)idx * 4] = v;
}

// ---------------- launch ----------------------------------------------------
extern "C" void kernel_launch(void* const* d_in, const int* in_sizes, int n_in,
                              void* d_out, int out_size)
{
    const float* x         = (const float*)d_in[0];
    const float* w_reduce  = (const float*)d_in[1];
    const float* w_lin     = (const float*)d_in[2];
    const float* att_src   = (const float*)d_in[3];
    const float* att_dst   = (const float*)d_in[4];
    const float* b_gat     = (const float*)d_in[5];
    const float* w_restore = (const float*)d_in[6];
    const float* bn_gamma  = (const float*)d_in[7];
    const float* bn_beta   = (const float*)d_in[8];
    // d_in[9]=src, d_in[10]=dst: structured 4-neighbor grid, recomputed analytically.

    k_prep<<<1, 256>>>(w_lin, att_src, att_dst);
    k_hfeat<<<BB * NN / 128, 512>>>(x, w_reduce, w_lin);
    k_agg<<<BB * NN / 8, 256>>>(b_gat);
    k_restore<<<BB * NN / 64, 256>>>(x, w_restore);
    k_bnstats<<<1, 64>>>(bn_gamma, bn_beta);
    k_bnrelu<<<(BB * COUT * NN / 4) / 256, 256>>>((float*)d_out);
}

// round 4
// speedup vs baseline: 1.9483x; 1.1111x over previous
#include <cuda_runtime.h>
#include <math.h>

#define BB    8
#define CIN   64
#define CR    32
#define HH    128
#define WW    128
#define NN    16384
#define COUT  64
#define CNT   (BB * NN)

// ---------------- device scratch ----------------
__device__ float g_q[8 * CR];                        // rows 0-3: q_src[h], 4-7: q_dst[h]
__device__ float g_xr[(size_t)BB * CR * NN];         // reduced features, plane-major [b][cr][N]  16 MB
__device__ float g_att[(size_t)BB * 8 * NN];         // [b][rq][N]: rq 0-3 a_src, 4-7 a_dst      4 MB
__device__ float g_pre[(size_t)BB * COUT * NN];      // pre-BN 33.5 MB
__device__ float g_sum[COUT];
__device__ float g_sumsq[COUT];
__device__ float g_scale[COUT];
__device__ float g_shift[COUT];

// ---------------- kernel 0: q-vectors + zero stats --------------------------
// q[rq][k] = sum_c att[h][c] * w_lin[h*32+c][k]  (attention scores are linear in xr)
__global__ void k_prep(const float* __restrict__ w_lin,
                       const float* __restrict__ att_src,
                       const float* __restrict__ att_dst)
{
    int idx = threadIdx.x;
    if (idx < 256) {
        int rq = idx >> 5, k = idx & 31;
        int h = rq & 3;
        const float* av = (rq < 4) ? att_src : att_dst;
        float acc = 0.f;
        #pragma unroll
        for (int c = 0; c < CR; c++)
            acc += av[h * CR + c] * w_lin[(h * CR + c) * CR + k];
        g_q[rq * CR + k] = acc;
    }
    if (idx < COUT) { g_sum[idx] = 0.f; g_sumsq[idx] = 0.f; }
}

// ---------------- kernel 1: xr = w_reduce @ x, attention rows ---------------
// 128 nodes / block, 256 threads.
__global__ __launch_bounds__(256) void k_xr(
    const float* __restrict__ x,
    const float* __restrict__ w_reduce)
{
    __shared__ float xs[CIN * 128];     // 32 KB; reused for xr [32][132] after stage 1
    __shared__ float wr_s[64 * 36];     // w_reduce^T [c][cr], padded
    __shared__ float qs[32 * 8];        // q^T [k][rq]

    const int t = threadIdx.x;
    const int b = blockIdx.x >> 7;
    const int nodeBase = (blockIdx.x & 127) << 7;

    #pragma unroll
    for (int i = 0; i < 32; i++) {
        int idx = t + i * 256;
        int c = idx >> 7, n = idx & 127;
        xs[idx] = x[((size_t)(b * CIN + c)) * NN + nodeBase + n];
    }
    #pragma unroll
    for (int i = 0; i < 8; i++) {
        int idx = t + i * 256;
        int cr = idx >> 6, c = idx & 63;
        wr_s[c * 36 + cr] = w_reduce[idx];
    }
    { int rq = t >> 5, k = t & 31; qs[k * 8 + rq] = g_q[t]; }
    __syncthreads();

    // xr = w_reduce @ xs : thread = (crq = t&7 -> 4 cr, n32 = t>>3 -> 4 nodes)
    const int crq = t & 7;
    const int n0  = (t >> 3) << 2;
    float a1[4][4];
    #pragma unroll
    for (int i = 0; i < 4; i++)
        #pragma unroll
        for (int j = 0; j < 4; j++) a1[i][j] = 0.f;

    #pragma unroll
    for (int c = 0; c < CIN; c++) {
        float4 wv = *(const float4*)&wr_s[c * 36 + crq * 4];
        float4 xv = *(const float4*)&xs[c * 128 + n0];
        a1[0][0] += wv.x * xv.x; a1[0][1] += wv.x * xv.y; a1[0][2] += wv.x * xv.z; a1[0][3] += wv.x * xv.w;
        a1[1][0] += wv.y * xv.x; a1[1][1] += wv.y * xv.y; a1[1][2] += wv.y * xv.z; a1[1][3] += wv.y * xv.w;
        a1[2][0] += wv.z * xv.x; a1[2][1] += wv.z * xv.y; a1[2][2] += wv.z * xv.z; a1[2][3] += wv.z * xv.w;
        a1[3][0] += wv.w * xv.x; a1[3][1] += wv.w * xv.y; a1[3][2] += wv.w * xv.z; a1[3][3] += wv.w * xv.w;
    }

    // write xr to global (plane-major, coalesced float4)
    #pragma unroll
    for (int i = 0; i < 4; i++) {
        float4 v = make_float4(a1[i][0], a1[i][1], a1[i][2], a1[i][3]);
        *(float4*)&g_xr[((size_t)(b * CR + crq * 4 + i)) * NN + nodeBase + n0] = v;
    }
    __syncthreads();     // xs reads done -> safe to overwrite with xr
    float* xrs = xs;     // [k][132]
    #pragma unroll
    for (int i = 0; i < 4; i++) {
        float4 v = make_float4(a1[i][0], a1[i][1], a1[i][2], a1[i][3]);
        *(float4*)&xrs[(crq * 4 + i) * 132 + n0] = v;
    }
    __syncthreads();

    // attention rows: warp rq (0..7), lane handles 4 nodes
    const int rq   = t >> 5;
    const int lane = t & 31;
    const int na   = lane << 2;
    float p0 = 0.f, p1 = 0.f, p2 = 0.f, p3 = 0.f;
    #pragma unroll
    for (int k = 0; k < CR; k++) {
        float qv = qs[k * 8 + rq];
        float4 xv = *(const float4*)&xrs[k * 132 + na];
        p0 += qv * xv.x; p1 += qv * xv.y; p2 += qv * xv.z; p3 += qv * xv.w;
    }
    *(float4*)&g_att[((size_t)(b * 8 + rq)) * NN + nodeBase + na] = make_float4(p0, p1, p2, p3);
}

// ---------------- kernel 2: fused agg + per-head GEMM + restore + BN stats --
// block = 64 nodes (half grid row), 256 threads, dynamic smem.
#define SM_XS   0          // [3*32][68]   xr rows i-1,i,i+1          6528 floats
#define SM_AL   6528       // [4*5][68]    alphas (0.25/den folded)   1360
#define SM_WH   7888       // [32][34]     W_h^T staging              1088
#define SM_Z    8976       // [32][68]     z_h / later nf             2176
#define SM_WR   11152      // [32][68]     w_restore^T                2176
#define SM_RED  13328      // 64*16 float2                            2048
#define SM_TOT  15376      // floats -> 61504 bytes

__global__ __launch_bounds__(256) void k_fused(
    const float* __restrict__ x,
    const float* __restrict__ w_lin,
    const float* __restrict__ w_restore,
    const float* __restrict__ b_gat)
{
    extern __shared__ float S[];
    float*  xs  = S + SM_XS;
    float*  al  = S + SM_AL;
    float*  Whs = S + SM_WH;
    float*  z   = S + SM_Z;
    float*  wrs = S + SM_WR;
    float2* red = (float2*)(S + SM_RED);

    const int t   = threadIdx.x;
    const int b   = blockIdx.x >> 8;
    const int rem = blockIdx.x & 255;
    const int i   = rem >> 1;
    const int j0  = (rem & 1) << 6;
    const size_t attB = (size_t)b * 8 * NN;

    // load w_restore^T [k][co]
    #pragma unroll
    for (int it = 0; it < 8; it++) {
        int idx = t + it * 256;
        int co = idx >> 5, k = idx & 31;
        wrs[k * 68 + co] = w_restore[idx];
    }
    // load xr halo: 3 rows x 32 cr x 66 cols (clamped)
    for (int idx = t; idx < 96 * 66; idx += 256) {
        int seg = idx / 66, slot = idx - seg * 66;
        int row3 = seg >> 5, cr = seg & 31;
        int srow = i - 1 + row3; srow = srow < 0 ? 0 : (srow > 127 ? 127 : srow);
        int col  = j0 - 1 + slot; col = col < 0 ? 0 : (col > 127 ? 127 : col);
        xs[seg * 68 + slot] = g_xr[((size_t)(b * CR + cr)) * NN + srow * 128 + col];
    }
    // alphas: thread = (h = t>>6, n = t&63)
    {
        const int h = t >> 6, n = t & 63;
        const int j = j0 + n;
        const int pos = i * 128 + j;
        const float* ps = &g_att[attB + (size_t)h * NN];
        const float* pd = &g_att[attB + (size_t)(4 + h) * NN];
        const float ad = pd[pos];
        const bool vu = (i > 0), vd = (i < HH - 1), vl = (j > 0), vr = (j < WW - 1);
        float e[5];
        float v;
        v = ps[pos] + ad;                       e[0] = v > 0.f ? v : 0.2f * v;
        v = (vu ? ps[pos - 128] : 0.f) + ad;    e[1] = vu ? (v > 0.f ? v : 0.2f * v) : -1e30f;
        v = (vd ? ps[pos + 128] : 0.f) + ad;    e[2] = vd ? (v > 0.f ? v : 0.2f * v) : -1e30f;
        v = (vl ? ps[pos - 1]   : 0.f) + ad;    e[3] = vl ? (v > 0.f ? v : 0.2f * v) : -1e30f;
        v = (vr ? ps[pos + 1]   : 0.f) + ad;    e[4] = vr ? (v > 0.f ? v : 0.2f * v) : -1e30f;
        float mx = e[0];
        #pragma unroll
        for (int s = 1; s < 5; s++) mx = fmaxf(mx, e[s]);
        float den = 0.f;
        #pragma unroll
        for (int s = 0; s < 5; s++) { e[s] = __expf(e[s] - mx); den += e[s]; }
        float sc = 0.25f / den;                 // head-mean folded in
        #pragma unroll
        for (int s = 0; s < 5; s++) al[(h * 5 + s) * 68 + n] = e[s] * sc;
    }
    __syncthreads();

    // per-head: z_h = sum_s alpha * xr[u_s];  nf += W_h @ z_h
    float acc[2][4];
    #pragma unroll
    for (int r = 0; r < 2; r++)
        #pragma unroll
        for (int c = 0; c < 4; c++) acc[r][c] = 0.f;

    const int co0g = (t & 15) * 2;      // gemm out-channel pair
    const int n0g  = (t >> 4) * 4;      // gemm node quad
    const int nz   = t & 63;            // z-build node
    const int cr8  = (t >> 6) * 8;      // z-build cr block

    for (int h = 0; h < 4; h++) {
        #pragma unroll
        for (int it = 0; it < 4; it++) {
            int idx = t + it * 256;
            int co = idx >> 5, k = idx & 31;
            Whs[k * 34 + co] = w_lin[(h * CR + co) * CR + k];
        }
        __syncthreads();

        {
            const float a0 = al[(h * 5 + 0) * 68 + nz];
            const float a1 = al[(h * 5 + 1) * 68 + nz];
            const float a2 = al[(h * 5 + 2) * 68 + nz];
            const float a3 = al[(h * 5 + 3) * 68 + nz];
            const float a4 = al[(h * 5 + 4) * 68 + nz];
            #pragma unroll
            for (int cc = 0; cc < 8; cc++) {
                int cr = cr8 + cc;
                float vv = a0 * xs[(32 + cr) * 68 + nz + 1]
                         + a1 * xs[(     cr) * 68 + nz + 1]
                         + a2 * xs[(64 + cr) * 68 + nz + 1]
                         + a3 * xs[(32 + cr) * 68 + nz]
                         + a4 * xs[(32 + cr) * 68 + nz + 2];
                z[cr * 68 + nz] = vv;
            }
        }
        __syncthreads();

        #pragma unroll
        for (int k = 0; k < CR; k++) {
            float w0 = Whs[k * 34 + co0g];
            float w1 = Whs[k * 34 + co0g + 1];
            float4 zv = *(const float4*)&z[k * 68 + n0g];
            acc[0][0] += w0 * zv.x; acc[0][1] += w0 * zv.y; acc[0][2] += w0 * zv.z; acc[0][3] += w0 * zv.w;
            acc[1][0] += w1 * zv.x; acc[1][1] += w1 * zv.y; acc[1][2] += w1 * zv.z; acc[1][3] += w1 * zv.w;
        }
        __syncthreads();
    }

    // nf (+bias) -> z buffer
    #pragma unroll
    for (int r = 0; r < 2; r++) {
        float bg = b_gat[co0g + r];
        float4 v = make_float4(acc[r][0] + bg, acc[r][1] + bg, acc[r][2] + bg, acc[r][3] + bg);
        *(float4*)&z[(co0g + r) * 68 + n0g] = v;
    }
    __syncthreads();

    // restore GEMM + residual + stats: thread = 4 co x 4 n
    const int co0 = (t & 15) * 4;
    const int tn  = t >> 4;
    const int n0  = tn * 4;
    float a2[4][4];
    #pragma unroll
    for (int r = 0; r < 4; r++)
        #pragma unroll
        for (int c = 0; c < 4; c++) a2[r][c] = 0.f;

    #pragma unroll
    for (int k = 0; k < CR; k++) {
        float4 wv = *(const float4*)&wrs[k * 68 + co0];
        float4 xv = *(const float4*)&z[k * 68 + n0];
        a2[0][0] += wv.x * xv.x; a2[0][1] += wv.x * xv.y; a2[0][2] += wv.x * xv.z; a2[0][3] += wv.x * xv.w;
        a2[1][0] += wv.y * xv.x; a2[1][1] += wv.y * xv.y; a2[1][2] += wv.y * xv.z; a2[1][3] += wv.y * xv.w;
        a2[2][0] += wv.z * xv.x; a2[2][1] += wv.z * xv.y; a2[2][2] += wv.z * xv.z; a2[2][3] += wv.z * xv.w;
        a2[3][0] += wv.w * xv.x; a2[3][1] += wv.w * xv.y; a2[3][2] += wv.w * xv.z; a2[3][3] += wv.w * xv.w;
    }

    #pragma unroll
    for (int r = 0; r < 4; r++) {
        size_t base = ((size_t)(b * COUT + co0 + r)) * NN + i * 128 + j0 + n0;
        float4 rv = *(const float4*)&x[base];
        float4 v  = make_float4(a2[r][0] + rv.x, a2[r][1] + rv.y,
                                a2[r][2] + rv.z, a2[r][3] + rv.w);
        *(float4*)&g_pre[base] = v;
        float s = v.x + v.y + v.z + v.w;
        float q = v.x * v.x + v.y * v.y + v.z * v.z + v.w * v.w;
        red[(co0 + r) * 16 + tn] = make_float2(s, q);
    }
    __syncthreads();

    if (t < COUT) {
        float s = 0.f, q = 0.f;
        #pragma unroll
        for (int jj = 0; jj < 16; jj++) {
            float2 v = red[t * 16 + jj];
            s += v.x; q += v.y;
        }
        atomicAdd(&g_sum[t],   s);
        atomicAdd(&g_sumsq[t], q);
    }
}

// ---------------- kernel C: finalize BN scale/shift -------------------------
__global__ void k_bnstats(const float* __restrict__ gamma,
                          const float* __restrict__ beta)
{
    int c = threadIdx.x;
    float inv_cnt = 1.f / (float)CNT;
    float mean = g_sum[c] * inv_cnt;
    float var  = g_sumsq[c] * inv_cnt - mean * mean;
    float sc   = gamma[c] / sqrtf(var + 1e-5f);
    g_scale[c] = sc;
    g_shift[c] = beta[c] - mean * sc;
}

// ---------------- kernel D: normalize + relu --------------------------------
__global__ __launch_bounds__(256) void k_bnrelu(float* __restrict__ out)
{
    int idx = blockIdx.x * blockDim.x + threadIdx.x;   // float4 index
    int c = (idx >> 12) & 63;
    float sc = g_scale[c], sh = g_shift[c];
    float4 v = *(const float4*)&g_pre[(size_t)idx * 4];
    v.x = fmaxf(0.f, v.x * sc + sh);
    v.y = fmaxf(0.f, v.y * sc + sh);
    v.z = fmaxf(0.f, v.z * sc + sh);
    v.w = fmaxf(0.f, v.w * sc + sh);
    *(float4*)&out[(size_t)idx * 4] = v;
}

// ---------------- launch -----------------------------------------------------
extern "C" void kernel_launch(void* const* d_in, const int* in_sizes, int n_in,
                              void* d_out, int out_size)
{
    const float* x         = (const float*)d_in[0];
    const float* w_reduce  = (const float*)d_in[1];
    const float* w_lin     = (const float*)d_in[2];
    const float* att_src   = (const float*)d_in[3];
    const float* att_dst   = (const float*)d_in[4];
    const float* b_gat     = (const float*)d_in[5];
    const float* w_restore = (const float*)d_in[6];
    const float* bn_gamma  = (const float*)d_in[7];
    const float* bn_beta   = (const float*)d_in[8];
    // d_in[9]=src, d_in[10]=dst: structured 4-neighbor grid, recomputed analytically.

    static int smem_set = 0;
    if (!smem_set) {
        cudaFuncSetAttribute(k_fused, cudaFuncAttributeMaxDynamicSharedMemorySize,
                             SM_TOT * (int)sizeof(float));
        smem_set = 1;
    }

    k_prep<<<1, 256>>>(w_lin, att_src, att_dst);
    k_xr<<<BB * NN / 128, 256>>>(x, w_reduce);
    k_fused<<<BB * NN / 64, 256, SM_TOT * sizeof(float)>>>(x, w_lin, w_restore, b_gat);
    k_bnstats<<<1, 64>>>(bn_gamma, bn_beta);
    k_bnrelu<<<(BB * COUT * NN / 4) / 256, 256>>>((float*)d_out);
}